// round 11
// baseline (speedup 1.0000x reference)
#include <cuda_runtime.h>
#include <cstddef>

// Hin2vec layer: B=262144, N=1e6, R=64, H=128.
// R10: R6 structure (4 elems/warp, MLP=8 gathers, 8192 blocks, no reg cap)
// with a restructured 13-shuffle reduction (was 22) to relieve MIO pressure:
// 2 butterfly stages on 4 accumulators -> quadrant select -> 3 stages.

#define H_DIM 128
#define R_DIM 64
#define WPB   8      // warps per block
#define ELEMS 4      // elements per warp

__device__ float d_reWr[R_DIM * H_DIM];   // 32 KB: s*(1-s) of clamp(Wr)

__global__ void hin_prep(const float* __restrict__ Wr, float* __restrict__ loss_ptr) {
    const int t = blockIdx.x * blockDim.x + threadIdx.x;
    if (t < R_DIM * H_DIM) {
        float e = fminf(fmaxf(Wr[t], -6.0f), 6.0f);
        float s = 1.0f / (1.0f + __expf(-e));
        d_reWr[t] = s * (1.0f - s);
    }
    if (t == 0 && loss_ptr) *loss_ptr = 0.0f;
}

__device__ __forceinline__ float dot_rw(float4 a, float4 b, float4 w) {
    float acc = a.x * b.x * w.x;
    acc = fmaf(a.y * b.y, w.y, acc);
    acc = fmaf(a.z * b.z, w.z, acc);
    acc = fmaf(a.w * b.w, w.w, acc);
    return acc;
}

__global__ void __launch_bounds__(WPB * 32)
hin_main(const int* __restrict__ x,
         const int* __restrict__ y,
         const int* __restrict__ r,
         const int* __restrict__ l,
         const float4* __restrict__ Wx,   // [N, H/4]
         float* __restrict__ out,         // [B, 2] logits
         float* __restrict__ loss_out,    // scalar (may be null)
         int B, float invB)
{
    const int wid  = threadIdx.x >> 5;
    const int lane = threadIdx.x & 31;
    const int base = (blockIdx.x * WPB + wid) * ELEMS;

    __shared__ float sloss[WPB];
    float my_loss = 0.0f;

    if (base < B) {
        // Broadcast index loads (all lanes same address -> 1 sector each).
        const int4 xv = *(const int4*)(x + base);
        const int4 yv = *(const int4*)(y + base);

        // Issue all 8 random 512B gathers before any dependent work (MLP=8).
        const float4 ax0 = __ldcg(Wx + (unsigned)xv.x * (H_DIM / 4) + lane);
        const float4 ay0 = __ldcg(Wx + (unsigned)yv.x * (H_DIM / 4) + lane);
        const float4 ax1 = __ldcg(Wx + (unsigned)xv.y * (H_DIM / 4) + lane);
        const float4 ay1 = __ldcg(Wx + (unsigned)yv.y * (H_DIM / 4) + lane);
        const float4 ax2 = __ldcg(Wx + (unsigned)xv.z * (H_DIM / 4) + lane);
        const float4 ay2 = __ldcg(Wx + (unsigned)yv.z * (H_DIM / 4) + lane);
        const float4 ax3 = __ldcg(Wx + (unsigned)xv.w * (H_DIM / 4) + lane);
        const float4 ay3 = __ldcg(Wx + (unsigned)yv.w * (H_DIM / 4) + lane);

        // Regularization rows from the hot, L1-resident 32KB table.
        const int4 rv = *(const int4*)(r + base);
        const float4* RW = (const float4*)d_reWr;
        const float4 rw0 = __ldg(RW + (unsigned)rv.x * (H_DIM / 4) + lane);
        const float4 rw1 = __ldg(RW + (unsigned)rv.y * (H_DIM / 4) + lane);
        const float4 rw2 = __ldg(RW + (unsigned)rv.z * (H_DIM / 4) + lane);
        const float4 rw3 = __ldg(RW + (unsigned)rv.w * (H_DIM / 4) + lane);

        float a0 = dot_rw(ax0, ay0, rw0);
        float a1 = dot_rw(ax1, ay1, rw1);
        float a2 = dot_rw(ax2, ay2, rw2);
        float a3 = dot_rw(ax3, ay3, rw3);

        // Stage A: two butterfly stages on all four accumulators (8 SHFL).
        // Afterwards lane i holds each a_j summed over coset {i, i^8, i^16, i^24}.
        #pragma unroll
        for (int o = 16; o >= 8; o >>= 1) {
            a0 += __shfl_xor_sync(0xFFFFFFFFu, a0, o);
            a1 += __shfl_xor_sync(0xFFFFFFFFu, a1, o);
            a2 += __shfl_xor_sync(0xFFFFFFFFu, a2, o);
            a3 += __shfl_xor_sync(0xFFFFFFFFu, a3, o);
        }

        // Stage B: quadrant select -> one value per lane (group q owns a_q).
        const int q = lane >> 3;
        float v = (q == 0) ? a0 : (q == 1) ? a1 : (q == 2) ? a2 : a3;

        // Stage C: finish within each 8-lane group (3 SHFL).
        v += __shfl_xor_sync(0xFFFFFFFFu, v, 4);
        v += __shfl_xor_sync(0xFFFFFFFFu, v, 2);
        v += __shfl_xor_sync(0xFFFFFFFFu, v, 1);
        // Now every lane of group q holds total(a_q).

        // Epilogue: one lane per 8-lane group (lanes 0,8,16,24), element base+q.
        if ((lane & 7) == 0) {
            const float p = 1.0f / (1.0f + __expf(-v));

            float2 lg;                       // 4 float2 stores -> one 32B sector
            lg.x = p;
            lg.y = 1.0f - p;
            __stcs(reinterpret_cast<float2*>(out) + base + q, lg);

            if (loss_out) {
                const float ea  = __expf(p);
                const float eb  = __expf(1.0f - p);
                const float lse = __logf(ea + eb);
                const int   li  = __ldg(l + base + q);
                const float chosen = (li == 0) ? p : (1.0f - p);
                my_loss = (lse - chosen) * invB;
            }
        }
    }

    if (loss_out) {
        // Lanes 0,8,16,24 hold partials; fold with 2 shuffles.
        my_loss += __shfl_xor_sync(0xFFFFFFFFu, my_loss, 8);
        my_loss += __shfl_xor_sync(0xFFFFFFFFu, my_loss, 16);
        if (lane == 0) sloss[wid] = my_loss;
        __syncthreads();
        if (threadIdx.x == 0) {
            float s = 0.0f;
            #pragma unroll
            for (int w = 0; w < WPB; w++) s += sloss[w];
            atomicAdd(loss_out, s);
        }
    }
}

extern "C" void kernel_launch(void* const* d_in, const int* in_sizes, int n_in,
                              void* d_out, int out_size)
{
    const int*    x  = (const int*)d_in[0];
    const int*    y  = (const int*)d_in[1];
    const int*    r  = (const int*)d_in[2];
    const int*    l  = (const int*)d_in[3];
    const float4* Wx = (const float4*)d_in[4];
    const float*  Wr = (const float*)d_in[5];

    const int B = in_sizes[0];
    float* out = (float*)d_out;
    float* loss_ptr = (out_size > 2 * B) ? (out + 2 * B) : nullptr;

    hin_prep<<<(R_DIM * H_DIM + 255) / 256, 256>>>(Wr, loss_ptr);

    const int elems_per_block = WPB * ELEMS;
    const int blocks = (B + elems_per_block - 1) / elems_per_block;
    hin_main<<<blocks, WPB * 32>>>(
        x, y, r, l, Wx, out, loss_ptr, B, 1.0f / (float)B);
}

// round 13
// speedup vs baseline: 1.0800x; 1.0800x over previous
#include <cuda_runtime.h>
#include <cstddef>

// Hin2vec layer: B=262144, N=1e6, R=64, H=128.
// R12: persistent grid-stride warps at FULL residency (148 SMs x 5 blocks,
// regs capped <=48), 4 elems/warp-iteration (MLP=8 gathers), cross-iteration
// index prefetch. R7 structure, correctly sized grid.

#define H_DIM 128
#define R_DIM 64
#define WPB   8      // warps per block
#define ELEMS 4      // elements per warp-iteration
#define NBLOCKS (148 * 5)

__device__ float d_reWr[R_DIM * H_DIM];   // 32 KB: s*(1-s) of clamp(Wr)

__global__ void hin_prep(const float* __restrict__ Wr, float* __restrict__ loss_ptr) {
    const int t = blockIdx.x * blockDim.x + threadIdx.x;
    if (t < R_DIM * H_DIM) {
        float e = fminf(fmaxf(Wr[t], -6.0f), 6.0f);
        float s = 1.0f / (1.0f + __expf(-e));
        d_reWr[t] = s * (1.0f - s);
    }
    if (t == 0 && loss_ptr) *loss_ptr = 0.0f;
}

__device__ __forceinline__ float dot_rw(float4 a, float4 b, float4 w) {
    float acc = a.x * b.x * w.x;
    acc = fmaf(a.y * b.y, w.y, acc);
    acc = fmaf(a.z * b.z, w.z, acc);
    acc = fmaf(a.w * b.w, w.w, acc);
    return acc;
}

__global__ void __launch_bounds__(WPB * 32, 5)   // keep regs <= 48 -> 5 blocks/SM
hin_main(const int* __restrict__ x,
         const int* __restrict__ y,
         const int* __restrict__ r,
         const int* __restrict__ l,
         const float4* __restrict__ Wx,   // [N, H/4]
         float* __restrict__ out,         // [B, 2] logits
         float* __restrict__ loss_out,    // scalar (may be null)
         int B, float invB)
{
    const int wid    = threadIdx.x >> 5;
    const int lane   = threadIdx.x & 31;
    const int nwarps = gridDim.x * WPB;
    const int nchunk = B >> 2;                    // B % 4 == 0

    __shared__ float sloss[WPB];
    float loss_acc = 0.0f;

    int chunk = blockIdx.x * WPB + wid;

    // Prime: indices for the first chunk.
    int4 xv, yv;
    if (chunk < nchunk) {
        xv = *(const int4*)(x + chunk * ELEMS);
        yv = *(const int4*)(y + chunk * ELEMS);
    }

    while (chunk < nchunk) {
        const int base = chunk * ELEMS;

        // Issue all 8 random 512B gathers first (MLP=8, L2-only hint).
        const float4 ax0 = __ldcg(Wx + (unsigned)xv.x * (H_DIM / 4) + lane);
        const float4 ay0 = __ldcg(Wx + (unsigned)yv.x * (H_DIM / 4) + lane);
        const float4 ax1 = __ldcg(Wx + (unsigned)xv.y * (H_DIM / 4) + lane);
        const float4 ay1 = __ldcg(Wx + (unsigned)yv.y * (H_DIM / 4) + lane);
        const float4 ax2 = __ldcg(Wx + (unsigned)xv.z * (H_DIM / 4) + lane);
        const float4 ay2 = __ldcg(Wx + (unsigned)yv.z * (H_DIM / 4) + lane);
        const float4 ax3 = __ldcg(Wx + (unsigned)xv.w * (H_DIM / 4) + lane);
        const float4 ay3 = __ldcg(Wx + (unsigned)yv.w * (H_DIM / 4) + lane);

        // Prefetch next iteration's indices while gathers are in flight.
        const int next = chunk + nwarps;
        int4 xn, yn;
        if (next < nchunk) {
            xn = *(const int4*)(x + next * ELEMS);
            yn = *(const int4*)(y + next * ELEMS);
        }

        // Regularization rows from the hot 32KB L1-resident table.
        const int4 rv = *(const int4*)(r + base);
        const float4* RW = (const float4*)d_reWr;
        const float4 rw0 = __ldg(RW + (unsigned)rv.x * (H_DIM / 4) + lane);
        const float4 rw1 = __ldg(RW + (unsigned)rv.y * (H_DIM / 4) + lane);
        const float4 rw2 = __ldg(RW + (unsigned)rv.z * (H_DIM / 4) + lane);
        const float4 rw3 = __ldg(RW + (unsigned)rv.w * (H_DIM / 4) + lane);

        float a0 = dot_rw(ax0, ay0, rw0);
        float a1 = dot_rw(ax1, ay1, rw1);
        float a2 = dot_rw(ax2, ay2, rw2);
        float a3 = dot_rw(ax3, ay3, rw3);

        // Four interleaved butterfly reductions.
        #pragma unroll
        for (int o = 16; o > 0; o >>= 1) {
            a0 += __shfl_xor_sync(0xFFFFFFFFu, a0, o);
            a1 += __shfl_xor_sync(0xFFFFFFFFu, a1, o);
            a2 += __shfl_xor_sync(0xFFFFFFFFu, a2, o);
            a3 += __shfl_xor_sync(0xFFFFFFFFu, a3, o);
        }

        // Lanes 0..3 each finish one element.
        if (lane < ELEMS) {
            const float acc = (lane == 0) ? a0 : (lane == 1) ? a1 : (lane == 2) ? a2 : a3;
            const float p = 1.0f / (1.0f + __expf(-acc));

            float2 lg;
            lg.x = p;
            lg.y = 1.0f - p;
            reinterpret_cast<float2*>(out)[base + lane] = lg;

            if (loss_out) {
                const float ea  = __expf(p);
                const float eb  = __expf(1.0f - p);
                const float lse = __logf(ea + eb);
                const int   li  = __ldg(l + base + lane);
                const float chosen = (li == 0) ? p : (1.0f - p);
                loss_acc += (lse - chosen) * invB;
            }
        }

        xv = xn; yv = yn;
        chunk = next;
    }

    if (loss_out) {
        // Fold lanes 0..3 partials; other lanes hold 0.
        loss_acc += __shfl_xor_sync(0xFFFFFFFFu, loss_acc, 1);
        loss_acc += __shfl_xor_sync(0xFFFFFFFFu, loss_acc, 2);
        if (lane == 0) sloss[wid] = loss_acc;
        __syncthreads();
        if (threadIdx.x == 0) {
            float s = 0.0f;
            #pragma unroll
            for (int w = 0; w < WPB; w++) s += sloss[w];
            atomicAdd(loss_out, s);
        }
    }
}

extern "C" void kernel_launch(void* const* d_in, const int* in_sizes, int n_in,
                              void* d_out, int out_size)
{
    const int*    x  = (const int*)d_in[0];
    const int*    y  = (const int*)d_in[1];
    const int*    r  = (const int*)d_in[2];
    const int*    l  = (const int*)d_in[3];
    const float4* Wx = (const float4*)d_in[4];
    const float*  Wr = (const float*)d_in[5];

    const int B = in_sizes[0];
    float* out = (float*)d_out;
    float* loss_ptr = (out_size > 2 * B) ? (out + 2 * B) : nullptr;

    hin_prep<<<(R_DIM * H_DIM + 255) / 256, 256>>>(Wr, loss_ptr);

    hin_main<<<NBLOCKS, WPB * 32>>>(
        x, y, r, l, Wx, out, loss_ptr, B, 1.0f / (float)B);
}